// round 1
// baseline (speedup 1.0000x reference)
#include <cuda_runtime.h>
#include <cstdint>

#define B_    256
#define DIN   700
#define T_    250
#define H_    1024
#define DOUT  20
#define NW    8        // 32-bit words covering T_=250 bits
#define DINP  704      // padded DIN
#define MAXL  256      // max active inputs per (b,t) list
#define NROW  (B_*T_)  // 64000
#define HS    64       // h columns per phase-A block slice
#define NBG   9        // b-groups in phase A
#define BPB   29       // b per group (9*29=261 >= 256)

// ---------------- scratch (static device memory; no allocations) -------------
__device__ float          g_Wt[DIN*H_];                     // W_hid^T  [i][h]
__device__ float          g_WoT[H_*DOUT];                   // W_out^T  [h][o]
__device__ unsigned       g_words[B_*NW*DINP];              // spike bits [(b*8+w)*704 + i], bit = t%32
__device__ unsigned short g_lists[(size_t)NROW*MAXL];       // active input indices per (b,t)
__device__ int            g_counts[NROW];
__device__ float          g_I[(size_t)NROW*H_];             // hidden input currents [b][t][h]
__device__ unsigned       g_hsb[(size_t)NROW*(H_/32)];      // hidden spike bits [b][t][h/32]
__device__ float          g_O[(size_t)NROW*DOUT];           // out-layer currents [b][t][o]

// ---------------- K0: pack spike_data -> bitmasks ----------------------------
__global__ void k_pack(const float* __restrict__ sd) {
    int gw   = blockIdx.x * 8 + (threadIdx.x >> 5);   // warp over B_*DIN rows
    int lane = threadIdx.x & 31;
    if (gw >= B_ * DIN) return;
    int b = gw / DIN, i = gw % DIN;
    const float* p = sd + ((size_t)b * DIN + i) * T_;
#pragma unroll
    for (int w = 0; w < NW; w++) {
        int t = w * 32 + lane;
        float v = (t < T_) ? p[t] : 0.0f;
        unsigned m = __ballot_sync(0xffffffffu, v > 0.5f);
        if (lane == 0) g_words[(b * NW + w) * DINP + i] = m;
    }
}

// ---------------- K1: transposes ---------------------------------------------
__global__ void k_tr(const float* __restrict__ Wh, const float* __restrict__ Wo) {
    int total = DIN * H_ + H_ * DOUT;
    for (int e = blockIdx.x * blockDim.x + threadIdx.x; e < total; e += gridDim.x * blockDim.x) {
        if (e < DIN * H_) {
            int i = e / H_, h = e % H_;
            g_Wt[e] = Wh[h * DIN + i];
        } else {
            int e2 = e - DIN * H_;
            int h = e2 / DOUT, o = e2 % DOUT;
            g_WoT[e2] = Wo[o * H_ + h];
        }
    }
}

// ---------------- K2a: deterministic active-index lists ----------------------
__global__ void k_lists() {
    __shared__ unsigned sw[DINP];
    int b = blockIdx.x / NW, w = blockIdx.x % NW;
    for (int i = threadIdx.x; i < DIN; i += blockDim.x)
        sw[i] = g_words[(b * NW + w) * DINP + i];
    __syncthreads();
    int wi = threadIdx.x >> 5, lane = threadIdx.x & 31;
    for (int tt = wi; tt < 32; tt += 8) {
        int t = w * 32 + tt;
        if (t >= T_) continue;
        int row = b * T_ + t;
        unsigned short* lst = &g_lists[(size_t)row * MAXL];
        int cnt = 0;
        for (int base = 0; base < DINP; base += 32) {
            int i = base + lane;
            unsigned hit = (i < DIN) ? ((sw[i] >> tt) & 1u) : 0u;
            unsigned m = __ballot_sync(0xffffffffu, hit != 0u);
            if (hit) {
                int pos = cnt + __popc(m & ((1u << lane) - 1u));
                if (pos < MAXL) lst[pos] = (unsigned short)i;
            }
            cnt += __popc(m);
        }
        if (lane == 0) g_counts[row] = min(cnt, MAXL);
    }
}

// ---------------- K2b: sparse hidden GEMM (I = xs @ W_hid^T) -----------------
// Block: one 64-wide h slice of W_hid^T cached in smem (179 KB); warps walk
// (b,t) pairs of a b-group, summing W rows listed in the active-index list.
__global__ __launch_bounds__(512, 1) void k_phaseA() {
    extern __shared__ float sW[];                // [DIN][HS]
    int hsIdx = blockIdx.x / NBG;
    int bg    = blockIdx.x % NBG;
    int h0    = hsIdx * HS;

    // load W slice (coalesced float4)
    for (int e = threadIdx.x; e < DIN * (HS / 4); e += blockDim.x) {
        int i = e / (HS / 4), c = e % (HS / 4);
        ((float4*)sW)[i * (HS / 4) + c] = *(const float4*)&g_Wt[i * H_ + h0 + c * 4];
    }
    __syncthreads();

    int warpId = threadIdx.x >> 5, lane = threadIdx.x & 31;
    int wp = warpId >> 1;            // pair slot 0..7
    int half = warpId & 1;           // which 32-h half of the slice
    int hh = half * 32 + lane;

    int bstart = bg * BPB;
    int nb = min(BPB, B_ - bstart);
    int npairs = nb * T_;

    for (int p = wp; p < npairs; p += 8) {
        int b = bstart + p / T_;
        int t = p % T_;
        int row = b * T_ + t;
        int cnt = g_counts[row];
        const unsigned short* lst = &g_lists[(size_t)row * MAXL];
        float acc = 0.0f;
        for (int base = 0; base < cnt; base += 32) {
            int myidx = (base + lane < cnt) ? (int)lst[base + lane] : 0;
            int n = min(32, cnt - base);
            if (n == 32) {
#pragma unroll
                for (int jj = 0; jj < 32; jj++) {
                    int idx = __shfl_sync(0xffffffffu, myidx, jj);
                    acc += sW[idx * HS + hh];
                }
            } else {
                for (int jj = 0; jj < n; jj++) {
                    int idx = __shfl_sync(0xffffffffu, myidx, jj);
                    acc += sW[idx * HS + hh];
                }
            }
        }
        g_I[(size_t)row * H_ + h0 + hh] = acc;
    }
}

// ---------------- K3: hidden LIF recurrence + spike-bit pack -----------------
__global__ void k_rec_hid(const float* __restrict__ hs0, const float* __restrict__ hv0) {
    int b  = blockIdx.x >> 2;
    int hq = blockIdx.x & 3;
    int h  = hq * 256 + threadIdx.x;
    int lane = threadIdx.x & 31;
    float hv = hv0[b * H_ + h];
    float hs = hs0[b * H_ + h];
    const float* Ip = &g_I[(size_t)(b * T_) * H_ + h];
    unsigned* hp = &g_hsb[(size_t)(b * T_) * (H_ / 32) + (h >> 5)];

    for (int t = 0; t < T_; t += 5) {            // 250 % 5 == 0
        float v[5];
#pragma unroll
        for (int k = 0; k < 5; k++) v[k] = Ip[(size_t)(t + k) * H_];
#pragma unroll
        for (int k = 0; k < 5; k++) {
            hv = hv * 0.5f * (1.0f - hs) + v[k];
            bool s = hv > 0.5f;
            hs = s ? 1.0f : 0.0f;
            unsigned m = __ballot_sync(0xffffffffu, s);
            if (lane == 0) hp[(size_t)(t + k) * (H_ / 32)] = m;
        }
    }
}

// ---------------- K4: out GEMM  O = hs @ W_out^T ------------------------------
__global__ void k_outgemm() {
    extern __shared__ float sWT[];               // [H_][DOUT] = 80 KB
    for (int e = threadIdx.x; e < H_ * DOUT / 4; e += blockDim.x)
        ((float4*)sWT)[e] = ((const float4*)g_WoT)[e];
    __syncthreads();

    int b = blockIdx.x;
    int wi = threadIdx.x >> 5, lane = threadIdx.x & 31;
    int t = wi * 32 + lane;
    bool valid = t < T_;
    int row = b * T_ + (valid ? t : 0);
    const unsigned* wp_ = &g_hsb[(size_t)row * (H_ / 32)];

    float acc[DOUT];
#pragma unroll
    for (int o = 0; o < DOUT; o++) acc[o] = 0.0f;

    for (int w = 0; w < H_ / 32; w++) {
        unsigned word = valid ? wp_[w] : 0u;
#pragma unroll
        for (int bit = 0; bit < 32; bit++) {
            float m = (float)((word >> bit) & 1u);
            const float* base = &sWT[(w * 32 + bit) * DOUT];
#pragma unroll
            for (int o4 = 0; o4 < 5; o4++) {
                float4 wv = *(const float4*)(base + o4 * 4);
                acc[o4 * 4 + 0] = fmaf(m, wv.x, acc[o4 * 4 + 0]);
                acc[o4 * 4 + 1] = fmaf(m, wv.y, acc[o4 * 4 + 1]);
                acc[o4 * 4 + 2] = fmaf(m, wv.z, acc[o4 * 4 + 2]);
                acc[o4 * 4 + 3] = fmaf(m, wv.w, acc[o4 * 4 + 3]);
            }
        }
    }
    if (valid) {
        float4* op = (float4*)&g_O[(size_t)row * DOUT];
#pragma unroll
        for (int o4 = 0; o4 < 5; o4++)
            op[o4] = make_float4(acc[o4 * 4 + 0], acc[o4 * 4 + 1], acc[o4 * 4 + 2], acc[o4 * 4 + 3]);
    }
}

// ---------------- K5: out LIF recurrence + spike counts -----------------------
__global__ void k_rec_out(const float* __restrict__ os0, const float* __restrict__ ov0,
                          float* __restrict__ out) {
    int b = blockIdx.x * (blockDim.x / 32) + (threadIdx.x >> 5);
    int o = threadIdx.x & 31;
    if (b >= B_ || o >= DOUT) return;
    float ov = ov0[b * DOUT + o];
    float os = os0[b * DOUT + o];
    float cnt = 0.0f;
    const float* Op = &g_O[(size_t)(b * T_) * DOUT + o];
    for (int tb = 0; tb < T_; tb += 10) {        // 250 % 10 == 0
        float v[10];
#pragma unroll
        for (int k = 0; k < 10; k++) v[k] = Op[(size_t)(tb + k) * DOUT];
#pragma unroll
        for (int k = 0; k < 10; k++) {
            ov = ov * 0.5f * (1.0f - os) + v[k];
            os = (ov > 0.5f) ? 1.0f : 0.0f;
            cnt += os;
        }
    }
    out[b * DOUT + o] = cnt;
}

// ---------------- launch ------------------------------------------------------
extern "C" void kernel_launch(void* const* d_in, const int* in_sizes, int n_in,
                              void* d_out, int out_size) {
    const float* sd  = (const float*)d_in[0];   // spike_data [256,700,250]
    const float* Wh  = (const float*)d_in[1];   // W_hid [1024,700]
    const float* Wo  = (const float*)d_in[2];   // W_out [20,1024]
    const float* hs0 = (const float*)d_in[3];   // hid_spike0 [256,1024]
    const float* hv0 = (const float*)d_in[4];   // hid_volt0
    const float* os0 = (const float*)d_in[5];   // out_spike0 [256,20]
    const float* ov0 = (const float*)d_in[6];   // out_volt0
    float* out = (float*)d_out;                 // [256,20] fp32
    (void)in_sizes; (void)n_in; (void)out_size;

    cudaFuncSetAttribute(k_phaseA, cudaFuncAttributeMaxDynamicSharedMemorySize, DIN * HS * 4);
    cudaFuncSetAttribute(k_outgemm, cudaFuncAttributeMaxDynamicSharedMemorySize, H_ * DOUT * 4);

    k_pack   <<<(B_ * DIN + 7) / 8, 256>>>(sd);
    k_tr     <<<256, 256>>>(Wh, Wo);
    k_lists  <<<B_ * NW, 256>>>();
    k_phaseA <<<16 * NBG, 512, DIN * HS * 4>>>();
    k_rec_hid<<<B_ * 4, 256>>>(hs0, hv0);
    k_outgemm<<<B_, 256, H_ * DOUT * 4>>>();
    k_rec_out<<<32, 256>>>(os0, ov0, out);
}

// round 2
// speedup vs baseline: 1.7288x; 1.7288x over previous
#include <cuda_runtime.h>
#include <cstdint>

#define B_    256
#define DIN   700
#define T_    250
#define H_    1024
#define DOUT  20
#define NW    8        // 32-bit words covering T_=250 bits
#define DINP  704      // padded DIN
#define MAXL  256      // max active inputs per (b,t) list
#define NROW  (B_*T_)  // 64000
#define HS    64       // h columns per phase-A block slice
#define NBG   9        // b-groups in phase A
#define BPB   29       // b per group (9*29=261 >= 256)

// ---------------- scratch (static device memory; no allocations) -------------
__device__ float          g_Wt[DIN*H_];                     // W_hid^T  [i][h]
__device__ float          g_WoT[H_*DOUT];                   // W_out^T  [h][o]
__device__ unsigned       g_words[B_*NW*DINP];              // spike bits [(b*8+w)*704 + i], bit = t%32
__device__ unsigned short g_lists[(size_t)NROW*MAXL];       // active input indices per (b,t)
__device__ int            g_counts[NROW];
__device__ float          g_I[(size_t)NROW*H_];             // hidden input currents [b][t][h]
__device__ unsigned       g_hsb[(size_t)NROW*(H_/32)];      // hidden spike bits [b][t][h/32]
__device__ float          g_O[(size_t)NROW*DOUT];           // out-layer currents [b][t][o]

// ---------------- K0: pack spike_data -> bitmasks ----------------------------
__global__ void k_pack(const float* __restrict__ sd) {
    int gw   = blockIdx.x * 8 + (threadIdx.x >> 5);   // warp over B_*DIN rows
    int lane = threadIdx.x & 31;
    if (gw >= B_ * DIN) return;
    int b = gw / DIN, i = gw % DIN;
    const float* p = sd + ((size_t)b * DIN + i) * T_;
#pragma unroll
    for (int w = 0; w < NW; w++) {
        int t = w * 32 + lane;
        float v = (t < T_) ? p[t] : 0.0f;
        unsigned m = __ballot_sync(0xffffffffu, v > 0.5f);
        if (lane == 0) g_words[(b * NW + w) * DINP + i] = m;
    }
}

// ---------------- K1: transposes ---------------------------------------------
__global__ void k_tr(const float* __restrict__ Wh, const float* __restrict__ Wo) {
    int total = DIN * H_ + H_ * DOUT;
    for (int e = blockIdx.x * blockDim.x + threadIdx.x; e < total; e += gridDim.x * blockDim.x) {
        if (e < DIN * H_) {
            int i = e / H_, h = e % H_;
            g_Wt[e] = Wh[h * DIN + i];
        } else {
            int e2 = e - DIN * H_;
            int h = e2 / DOUT, o = e2 % DOUT;
            g_WoT[e2] = Wo[o * H_ + h];
        }
    }
}

// ---------------- K2a: deterministic active-index lists ----------------------
__global__ void k_lists() {
    __shared__ unsigned sw[DINP];
    int b = blockIdx.x / NW, w = blockIdx.x % NW;
    for (int i = threadIdx.x; i < DIN; i += blockDim.x)
        sw[i] = g_words[(b * NW + w) * DINP + i];
    __syncthreads();
    int wi = threadIdx.x >> 5, lane = threadIdx.x & 31;
    for (int tt = wi; tt < 32; tt += 8) {
        int t = w * 32 + tt;
        if (t >= T_) continue;
        int row = b * T_ + t;
        unsigned short* lst = &g_lists[(size_t)row * MAXL];
        int cnt = 0;
        for (int base = 0; base < DINP; base += 32) {
            int i = base + lane;
            unsigned hit = (i < DIN) ? ((sw[i] >> tt) & 1u) : 0u;
            unsigned m = __ballot_sync(0xffffffffu, hit != 0u);
            if (hit) {
                int pos = cnt + __popc(m & ((1u << lane) - 1u));
                if (pos < MAXL) lst[pos] = (unsigned short)i;
            }
            cnt += __popc(m);
        }
        if (lane == 0) g_counts[row] = min(cnt, MAXL);
    }
}

// ---------------- K2b: sparse hidden GEMM (I = xs @ W_hid^T) -----------------
// One warp per (b,t) row per 64-wide h slice; float2 accumulators; W slice in
// smem (179 KB); 1024 threads/block for 32 warps/SM (occ 50%).
__global__ __launch_bounds__(1024, 1) void k_phaseA() {
    extern __shared__ float sW[];                // [DIN][HS]
    int hsIdx = blockIdx.x / NBG;
    int bg    = blockIdx.x % NBG;
    int h0    = hsIdx * HS;

    // load W slice (coalesced float4)
    for (int e = threadIdx.x; e < DIN * (HS / 4); e += blockDim.x) {
        int i = e / (HS / 4), c = e % (HS / 4);
        ((float4*)sW)[e] = *(const float4*)&g_Wt[i * H_ + h0 + c * 4];
    }
    __syncthreads();

    int warpId = threadIdx.x >> 5, lane = threadIdx.x & 31;
    const float2* sW2 = (const float2*)sW;       // sW2[idx*32 + lane] = h0+lane*2..+1

    int bstart = bg * BPB;
    int nb = min(BPB, B_ - bstart);
    int npairs = nb * T_;

    for (int p = warpId; p < npairs; p += 32) {
        int b = bstart + p / T_;
        int t = p % T_;
        int row = b * T_ + t;
        int cnt = g_counts[row];
        const unsigned short* lst = &g_lists[(size_t)row * MAXL];
        float ax = 0.0f, ay = 0.0f;
        for (int base = 0; base < cnt; base += 32) {
            int myidx = (base + lane < cnt) ? (int)lst[base + lane] : 0;
            int n = min(32, cnt - base);
            if (n == 32) {
#pragma unroll
                for (int jj = 0; jj < 32; jj++) {
                    int idx = __shfl_sync(0xffffffffu, myidx, jj);
                    float2 w = sW2[idx * 32 + lane];
                    ax += w.x; ay += w.y;
                }
            } else {
                for (int jj = 0; jj < n; jj++) {
                    int idx = __shfl_sync(0xffffffffu, myidx, jj);
                    float2 w = sW2[idx * 32 + lane];
                    ax += w.x; ay += w.y;
                }
            }
        }
        *(float2*)&g_I[(size_t)row * H_ + h0 + lane * 2] = make_float2(ax, ay);
    }
}

// ---------------- K3: hidden LIF recurrence + spike-bit pack -----------------
__global__ void k_rec_hid(const float* __restrict__ hs0, const float* __restrict__ hv0) {
    int b  = blockIdx.x >> 2;
    int hq = blockIdx.x & 3;
    int h  = hq * 256 + threadIdx.x;
    int lane = threadIdx.x & 31;
    float hv = hv0[b * H_ + h];
    float hs = hs0[b * H_ + h];
    const float* Ip = &g_I[(size_t)(b * T_) * H_ + h];
    unsigned* hp = &g_hsb[(size_t)(b * T_) * (H_ / 32) + (h >> 5)];

    for (int t = 0; t < T_; t += 5) {            // 250 % 5 == 0
        float v[5];
#pragma unroll
        for (int k = 0; k < 5; k++) v[k] = Ip[(size_t)(t + k) * H_];
#pragma unroll
        for (int k = 0; k < 5; k++) {
            hv = hv * 0.5f * (1.0f - hs) + v[k];
            bool s = hv > 0.5f;
            hs = s ? 1.0f : 0.0f;
            unsigned m = __ballot_sync(0xffffffffu, s);
            if (lane == 0) hp[(size_t)(t + k) * (H_ / 32)] = m;
        }
    }
}

// ---------------- K4: out GEMM  O = hs @ W_out^T ------------------------------
__global__ void k_outgemm() {
    extern __shared__ float sWT[];               // [H_][DOUT] = 80 KB
    for (int e = threadIdx.x; e < H_ * DOUT / 4; e += blockDim.x)
        ((float4*)sWT)[e] = ((const float4*)g_WoT)[e];
    __syncthreads();

    int b = blockIdx.x;
    int wi = threadIdx.x >> 5, lane = threadIdx.x & 31;
    int t = wi * 32 + lane;
    bool valid = t < T_;
    int row = b * T_ + (valid ? t : 0);
    const unsigned* wp_ = &g_hsb[(size_t)row * (H_ / 32)];

    float acc[DOUT];
#pragma unroll
    for (int o = 0; o < DOUT; o++) acc[o] = 0.0f;

    for (int w = 0; w < H_ / 32; w++) {
        unsigned word = valid ? wp_[w] : 0u;
        if (word == 0u) continue;
#pragma unroll
        for (int bit = 0; bit < 32; bit++) {
            float m = (float)((word >> bit) & 1u);
            const float* base = &sWT[(w * 32 + bit) * DOUT];
#pragma unroll
            for (int o4 = 0; o4 < 5; o4++) {
                float4 wv = *(const float4*)(base + o4 * 4);
                acc[o4 * 4 + 0] = fmaf(m, wv.x, acc[o4 * 4 + 0]);
                acc[o4 * 4 + 1] = fmaf(m, wv.y, acc[o4 * 4 + 1]);
                acc[o4 * 4 + 2] = fmaf(m, wv.z, acc[o4 * 4 + 2]);
                acc[o4 * 4 + 3] = fmaf(m, wv.w, acc[o4 * 4 + 3]);
            }
        }
    }
    if (valid) {
        float4* op = (float4*)&g_O[(size_t)row * DOUT];
#pragma unroll
        for (int o4 = 0; o4 < 5; o4++)
            op[o4] = make_float4(acc[o4 * 4 + 0], acc[o4 * 4 + 1], acc[o4 * 4 + 2], acc[o4 * 4 + 3]);
    }
}

// ---------------- K5: out LIF recurrence + spike counts -----------------------
__global__ void k_rec_out(const float* __restrict__ os0, const float* __restrict__ ov0,
                          float* __restrict__ out) {
    int b = blockIdx.x * (blockDim.x / 32) + (threadIdx.x >> 5);
    int o = threadIdx.x & 31;
    if (b >= B_ || o >= DOUT) return;
    float ov = ov0[b * DOUT + o];
    float os = os0[b * DOUT + o];
    float cnt = 0.0f;
    const float* Op = &g_O[(size_t)(b * T_) * DOUT + o];
    for (int tb = 0; tb < T_; tb += 10) {        // 250 % 10 == 0
        float v[10];
#pragma unroll
        for (int k = 0; k < 10; k++) v[k] = Op[(size_t)(tb + k) * DOUT];
#pragma unroll
        for (int k = 0; k < 10; k++) {
            ov = ov * 0.5f * (1.0f - os) + v[k];
            os = (ov > 0.5f) ? 1.0f : 0.0f;
            cnt += os;
        }
    }
    out[b * DOUT + o] = cnt;
}

// ---------------- launch ------------------------------------------------------
extern "C" void kernel_launch(void* const* d_in, const int* in_sizes, int n_in,
                              void* d_out, int out_size) {
    const float* sd  = (const float*)d_in[0];   // spike_data [256,700,250]
    const float* Wh  = (const float*)d_in[1];   // W_hid [1024,700]
    const float* Wo  = (const float*)d_in[2];   // W_out [20,1024]
    const float* hs0 = (const float*)d_in[3];   // hid_spike0 [256,1024]
    const float* hv0 = (const float*)d_in[4];   // hid_volt0
    const float* os0 = (const float*)d_in[5];   // out_spike0 [256,20]
    const float* ov0 = (const float*)d_in[6];   // out_volt0
    float* out = (float*)d_out;                 // [256,20] fp32
    (void)in_sizes; (void)n_in; (void)out_size;

    cudaFuncSetAttribute(k_phaseA, cudaFuncAttributeMaxDynamicSharedMemorySize, DIN * HS * 4);
    cudaFuncSetAttribute(k_outgemm, cudaFuncAttributeMaxDynamicSharedMemorySize, H_ * DOUT * 4);

    k_pack   <<<(B_ * DIN + 7) / 8, 256>>>(sd);
    k_tr     <<<256, 256>>>(Wh, Wo);
    k_lists  <<<B_ * NW, 256>>>();
    k_phaseA <<<16 * NBG, 1024, DIN * HS * 4>>>();
    k_rec_hid<<<B_ * 4, 256>>>(hs0, hv0);
    k_outgemm<<<B_, 256, H_ * DOUT * 4>>>();
    k_rec_out<<<32, 256>>>(os0, ov0, out);
}

// round 5
// speedup vs baseline: 1.9064x; 1.1027x over previous
#include <cuda_runtime.h>
#include <cstdint>

#define B_    256
#define DIN   700
#define T_    250
#define H_    1024
#define DOUT  20
#define NW    8        // 32-bit words covering T_=250 bits
#define DINP  704      // padded DIN
#define MAXL  256      // max active inputs per (b,t) list (multiple of 8)
#define NROW  (B_*T_)  // 64000
#define HS    64       // h columns per phase-A block slice
#define NBG   9        // b-groups in phase A
#define BPB   29       // b per group (9*29=261 >= 256)
#define ZROW  DIN      // dummy zero W row index (row 700)

// ---------------- scratch (static device memory; no allocations) -------------
__device__ float          g_Wt[(DIN+1)*H_];                 // W_hid^T [i][h], row 700 = zeros
__device__ float          g_WoT[H_*DOUT];                   // W_out^T  [h][o]
__device__ unsigned       g_words[B_*NW*DINP];              // spike bits [(b*8+w)*704 + i], bit = t%32
__device__ unsigned short g_lists[(size_t)NROW*MAXL];       // active input indices per (b,t), padded w/ ZROW
__device__ int            g_counts[NROW];                   // padded counts (multiple of 8)
__device__ float          g_I[(size_t)NROW*H_];             // hidden input currents [b][t][h]
__device__ unsigned       g_hsb[(size_t)NROW*(H_/32)];      // hidden spike bits [b][t][h/32]
__device__ float          g_O[(size_t)NROW*DOUT];           // out-layer currents [b][t][o]

// ---------------- K0: pack spike_data -> bitmasks ----------------------------
__global__ void k_pack(const float* __restrict__ sd) {
    int gw   = blockIdx.x * 8 + (threadIdx.x >> 5);   // warp over B_*DIN rows
    int lane = threadIdx.x & 31;
    if (gw >= B_ * DIN) return;
    int b = gw / DIN, i = gw % DIN;
    const float* p = sd + ((size_t)b * DIN + i) * T_;
#pragma unroll
    for (int w = 0; w < NW; w++) {
        int t = w * 32 + lane;
        float v = (t < T_) ? p[t] : 0.0f;
        unsigned m = __ballot_sync(0xffffffffu, v > 0.5f);
        if (lane == 0) g_words[(b * NW + w) * DINP + i] = m;
    }
}

// ---------------- K1: transposes (W row 700 zeroed) ---------------------------
__global__ void k_tr(const float* __restrict__ Wh, const float* __restrict__ Wo) {
    int total = (DIN + 1) * H_ + H_ * DOUT;
    for (int e = blockIdx.x * blockDim.x + threadIdx.x; e < total; e += gridDim.x * blockDim.x) {
        if (e < (DIN + 1) * H_) {
            int i = e / H_, h = e % H_;
            g_Wt[e] = (i < DIN) ? Wh[h * DIN + i] : 0.0f;
        } else {
            int e2 = e - (DIN + 1) * H_;
            int h = e2 / DOUT, o = e2 % DOUT;
            g_WoT[e2] = Wo[o * H_ + h];
        }
    }
}

// ---------------- K2a: active-index lists, padded to multiple of 8 ------------
__global__ void k_lists() {
    __shared__ unsigned sw[DINP];
    int b = blockIdx.x / NW, w = blockIdx.x % NW;
    for (int i = threadIdx.x; i < DIN; i += blockDim.x)
        sw[i] = g_words[(b * NW + w) * DINP + i];
    __syncthreads();
    int wi = threadIdx.x >> 5, lane = threadIdx.x & 31;
    for (int tt = wi; tt < 32; tt += 8) {
        int t = w * 32 + tt;
        if (t >= T_) continue;
        int row = b * T_ + t;
        unsigned short* lst = &g_lists[(size_t)row * MAXL];
        int cnt = 0;
        for (int base = 0; base < DINP; base += 32) {
            int i = base + lane;
            unsigned hit = (i < DIN) ? ((sw[i] >> tt) & 1u) : 0u;
            unsigned m = __ballot_sync(0xffffffffu, hit != 0u);
            if (hit) {
                int pos = cnt + __popc(m & ((1u << lane) - 1u));
                if (pos < MAXL) lst[pos] = (unsigned short)i;
            }
            cnt += __popc(m);
        }
        cnt = min(cnt, MAXL);
        int cnt_pad = (cnt + 7) & ~7;                 // pad to multiple of 8
        if (cnt + lane < cnt_pad) lst[cnt + lane] = (unsigned short)ZROW;  // dummy zero row
        if (lane == 0) g_counts[row] = cnt_pad;
    }
}

// ---------------- K2b: sparse hidden GEMM (I = xs @ W_hid^T) -----------------
// One warp per (b,t) row per 64-wide h slice; float2 accumulators; W slice
// (incl. zero row 700) in smem; indices read 8-at-a-time via broadcast LDG.128.
__global__ __launch_bounds__(1024, 1) void k_phaseA() {
    extern __shared__ float sW[];                // [(DIN+1)][HS]
    int hsIdx = blockIdx.x / NBG;
    int bg    = blockIdx.x % NBG;
    int h0    = hsIdx * HS;

    // load W slice (coalesced float4), 701 rows
    for (int e = threadIdx.x; e < (DIN + 1) * (HS / 4); e += blockDim.x) {
        int i = e / (HS / 4), c = e % (HS / 4);
        ((float4*)sW)[e] = *(const float4*)&g_Wt[i * H_ + h0 + c * 4];
    }
    __syncthreads();

    int warpId = threadIdx.x >> 5, lane = threadIdx.x & 31;
    const float2* sW2 = (const float2*)sW + lane;  // sW2[idx*32] = {h0+2lane, +1}

    int bstart = bg * BPB;
    int nb = min(BPB, B_ - bstart);
    int npairs = nb * T_;

    for (int p = warpId; p < npairs; p += 32) {
        int b = bstart + p / T_;
        int t = p % T_;
        int row = b * T_ + t;
        int cnt = g_counts[row];                   // multiple of 8
        const unsigned short* lst = &g_lists[(size_t)row * MAXL];
        float ax = 0.0f, ay = 0.0f;
        for (int base = 0; base < cnt; base += 8) {
            uint4 pk = *(const uint4*)(lst + base);   // broadcast LDG.128: 8 u16 indices
            unsigned i0 = pk.x & 0xFFFFu, i1 = pk.x >> 16;
            unsigned i2 = pk.y & 0xFFFFu, i3 = pk.y >> 16;
            unsigned i4 = pk.z & 0xFFFFu, i5 = pk.z >> 16;
            unsigned i6 = pk.w & 0xFFFFu, i7 = pk.w >> 16;
            float2 w0 = sW2[i0 * 32]; ax += w0.x; ay += w0.y;
            float2 w1 = sW2[i1 * 32]; ax += w1.x; ay += w1.y;
            float2 w2 = sW2[i2 * 32]; ax += w2.x; ay += w2.y;
            float2 w3 = sW2[i3 * 32]; ax += w3.x; ay += w3.y;
            float2 w4 = sW2[i4 * 32]; ax += w4.x; ay += w4.y;
            float2 w5 = sW2[i5 * 32]; ax += w5.x; ay += w5.y;
            float2 w6 = sW2[i6 * 32]; ax += w6.x; ay += w6.y;
            float2 w7 = sW2[i7 * 32]; ax += w7.x; ay += w7.y;
        }
        *(float2*)&g_I[(size_t)row * H_ + h0 + lane * 2] = make_float2(ax, ay);
    }
}

// ---------------- K3: hidden LIF recurrence + spike-bit pack -----------------
__global__ void k_rec_hid(const float* __restrict__ hs0, const float* __restrict__ hv0) {
    int b  = blockIdx.x >> 2;
    int hq = blockIdx.x & 3;
    int h  = hq * 256 + threadIdx.x;
    int lane = threadIdx.x & 31;
    float hv = hv0[b * H_ + h];
    float hs = hs0[b * H_ + h];
    const float* Ip = &g_I[(size_t)(b * T_) * H_ + h];
    unsigned* hp = &g_hsb[(size_t)(b * T_) * (H_ / 32) + (h >> 5)];

    for (int t = 0; t < T_; t += 5) {            // 250 % 5 == 0
        float v[5];
#pragma unroll
        for (int k = 0; k < 5; k++) v[k] = Ip[(size_t)(t + k) * H_];
#pragma unroll
        for (int k = 0; k < 5; k++) {
            hv = hv * 0.5f * (1.0f - hs) + v[k];
            bool s = hv > 0.5f;
            hs = s ? 1.0f : 0.0f;
            unsigned m = __ballot_sync(0xffffffffu, s);
            if (lane == 0) hp[(size_t)(t + k) * (H_ / 32)] = m;
        }
    }
}

// ---------------- K4: out GEMM  O = hs @ W_out^T ------------------------------
__global__ void k_outgemm() {
    extern __shared__ float sWT[];               // [H_][DOUT] = 80 KB
    for (int e = threadIdx.x; e < H_ * DOUT / 4; e += blockDim.x)
        ((float4*)sWT)[e] = ((const float4*)g_WoT)[e];
    __syncthreads();

    int b = blockIdx.x;
    int wi = threadIdx.x >> 5, lane = threadIdx.x & 31;
    int t = wi * 32 + lane;
    bool valid = t < T_;
    int row = b * T_ + (valid ? t : 0);
    const unsigned* wp_ = &g_hsb[(size_t)row * (H_ / 32)];

    float acc[DOUT];
#pragma unroll
    for (int o = 0; o < DOUT; o++) acc[o] = 0.0f;

    for (int w = 0; w < H_ / 32; w++) {
        unsigned word = valid ? wp_[w] : 0u;
        if (word == 0u) continue;
#pragma unroll
        for (int bit = 0; bit < 32; bit++) {
            float m = (float)((word >> bit) & 1u);
            const float* base = &sWT[(w * 32 + bit) * DOUT];
#pragma unroll
            for (int o4 = 0; o4 < 5; o4++) {
                float4 wv = *(const float4*)(base + o4 * 4);
                acc[o4 * 4 + 0] = fmaf(m, wv.x, acc[o4 * 4 + 0]);
                acc[o4 * 4 + 1] = fmaf(m, wv.y, acc[o4 * 4 + 1]);
                acc[o4 * 4 + 2] = fmaf(m, wv.z, acc[o4 * 4 + 2]);
                acc[o4 * 4 + 3] = fmaf(m, wv.w, acc[o4 * 4 + 3]);
            }
        }
    }
    if (valid) {
        float4* op = (float4*)&g_O[(size_t)row * DOUT];
#pragma unroll
        for (int o4 = 0; o4 < 5; o4++)
            op[o4] = make_float4(acc[o4 * 4 + 0], acc[o4 * 4 + 1], acc[o4 * 4 + 2], acc[o4 * 4 + 3]);
    }
}

// ---------------- K5: out LIF recurrence + spike counts -----------------------
__global__ void k_rec_out(const float* __restrict__ os0, const float* __restrict__ ov0,
                          float* __restrict__ out) {
    int b = blockIdx.x * (blockDim.x / 32) + (threadIdx.x >> 5);
    int o = threadIdx.x & 31;
    if (b >= B_ || o >= DOUT) return;
    float ov = ov0[b * DOUT + o];
    float os = os0[b * DOUT + o];
    float cnt = 0.0f;
    const float* Op = &g_O[(size_t)(b * T_) * DOUT + o];
    for (int tb = 0; tb < T_; tb += 10) {        // 250 % 10 == 0
        float v[10];
#pragma unroll
        for (int k = 0; k < 10; k++) v[k] = Op[(size_t)(tb + k) * DOUT];
#pragma unroll
        for (int k = 0; k < 10; k++) {
            ov = ov * 0.5f * (1.0f - os) + v[k];
            os = (ov > 0.5f) ? 1.0f : 0.0f;
            cnt += os;
        }
    }
    out[b * DOUT + o] = cnt;
}

// ---------------- launch ------------------------------------------------------
extern "C" void kernel_launch(void* const* d_in, const int* in_sizes, int n_in,
                              void* d_out, int out_size) {
    const float* sd  = (const float*)d_in[0];   // spike_data [256,700,250]
    const float* Wh  = (const float*)d_in[1];   // W_hid [1024,700]
    const float* Wo  = (const float*)d_in[2];   // W_out [20,1024]
    const float* hs0 = (const float*)d_in[3];   // hid_spike0 [256,1024]
    const float* hv0 = (const float*)d_in[4];   // hid_volt0
    const float* os0 = (const float*)d_in[5];   // out_spike0 [256,20]
    const float* ov0 = (const float*)d_in[6];   // out_volt0
    float* out = (float*)d_out;                 // [256,20] fp32
    (void)in_sizes; (void)n_in; (void)out_size;

    cudaFuncSetAttribute(k_phaseA, cudaFuncAttributeMaxDynamicSharedMemorySize, (DIN + 1) * HS * 4);
    cudaFuncSetAttribute(k_outgemm, cudaFuncAttributeMaxDynamicSharedMemorySize, H_ * DOUT * 4);

    k_pack   <<<(B_ * DIN + 7) / 8, 256>>>(sd);
    k_tr     <<<256, 256>>>(Wh, Wo);
    k_lists  <<<B_ * NW, 256>>>();
    k_phaseA <<<16 * NBG, 1024, (DIN + 1) * HS * 4>>>();
    k_rec_hid<<<B_ * 4, 256>>>(hs0, hv0);
    k_outgemm<<<B_, 256, H_ * DOUT * 4>>>();
    k_rec_out<<<32, 256>>>(os0, ov0, out);
}

// round 6
// speedup vs baseline: 1.9933x; 1.0456x over previous
#include <cuda_runtime.h>
#include <cstdint>

#define B_    256
#define DIN   700
#define T_    250
#define H_    1024
#define DOUT  20
#define NW    8        // 32-bit words covering T_=250 bits
#define DINP  704      // padded DIN
#define MAXL  256      // max active inputs per (b,t) list (multiple of 8)
#define NROW  (B_*T_)  // 64000
#define HS    64       // h columns per phase-A block slice
#define NBG   9        // b-groups in phase A
#define BPB   29       // b per group (9*29=261 >= 256)
#define ZROW  DIN      // dummy zero W row index (row 700)

// ---------------- scratch (static device memory; no allocations) -------------
__device__ float          g_Wt[(DIN+1)*H_];                 // W_hid^T [i][h], row 700 = zeros
__device__ float          g_WoT[H_*DOUT];                   // W_out^T  [h][o]
__device__ unsigned       g_words[B_*NW*DINP];              // spike bits [(b*8+w)*704 + i], bit = t%32
__device__ unsigned short g_lists[(size_t)NROW*MAXL];       // active input indices per (b,t), pair-padded
__device__ int            g_counts[NROW];                   // pair-max counts (multiple of 8)
__device__ float          g_I[(size_t)NROW*H_];             // hidden input currents [b][t][h]
__device__ unsigned       g_hsb[(size_t)NROW*(H_/32)];      // hidden spike bits [b][t][h/32]
__device__ float          g_O[(size_t)NROW*DOUT];           // out-layer currents [b][t][o]

// ---------------- K0: pack spike_data -> bitmasks ----------------------------
__global__ void k_pack(const float* __restrict__ sd) {
    int gw   = blockIdx.x * 8 + (threadIdx.x >> 5);   // warp over B_*DIN rows
    int lane = threadIdx.x & 31;
    if (gw >= B_ * DIN) return;
    int b = gw / DIN, i = gw % DIN;
    const float* p = sd + ((size_t)b * DIN + i) * T_;
#pragma unroll
    for (int w = 0; w < NW; w++) {
        int t = w * 32 + lane;
        float v = (t < T_) ? p[t] : 0.0f;
        unsigned m = __ballot_sync(0xffffffffu, v > 0.5f);
        if (lane == 0) g_words[(b * NW + w) * DINP + i] = m;
    }
}

// ---------------- K1: transposes (W row 700 zeroed) ---------------------------
__global__ void k_tr(const float* __restrict__ Wh, const float* __restrict__ Wo) {
    int total = (DIN + 1) * H_ + H_ * DOUT;
    for (int e = blockIdx.x * blockDim.x + threadIdx.x; e < total; e += gridDim.x * blockDim.x) {
        if (e < (DIN + 1) * H_) {
            int i = e / H_, h = e % H_;
            g_Wt[e] = (i < DIN) ? Wh[h * DIN + i] : 0.0f;
        } else {
            int e2 = e - (DIN + 1) * H_;
            int h = e2 / DOUT, o = e2 % DOUT;
            g_WoT[e2] = Wo[o * H_ + h];
        }
    }
}

// ---------------- K2a: active-index lists, pair-padded -------------------------
// Rows (t even, t+1) are padded to the same count so phaseA can process a pair
// per warp without predication. Padding index = ZROW (all-zero W row) -> exact.
__global__ void k_lists() {
    __shared__ unsigned sw[DINP];
    __shared__ int scnt[32];
    int b = blockIdx.x / NW, w = blockIdx.x % NW;
    for (int i = threadIdx.x; i < DIN; i += blockDim.x)
        sw[i] = g_words[(b * NW + w) * DINP + i];
    __syncthreads();
    int wi = threadIdx.x >> 5, lane = threadIdx.x & 31;
    for (int tt = wi; tt < 32; tt += 8) {
        int t = w * 32 + tt;
        if (t >= T_) { if (lane == 0) scnt[tt] = 0; continue; }
        int row = b * T_ + t;
        unsigned short* lst = &g_lists[(size_t)row * MAXL];
        int cnt = 0;
        for (int base = 0; base < DINP; base += 32) {
            int i = base + lane;
            unsigned hit = (i < DIN) ? ((sw[i] >> tt) & 1u) : 0u;
            unsigned m = __ballot_sync(0xffffffffu, hit != 0u);
            if (hit) {
                int pos = cnt + __popc(m & ((1u << lane) - 1u));
                if (pos < MAXL) lst[pos] = (unsigned short)i;
            }
            cnt += __popc(m);
        }
        cnt = min(cnt, MAXL);
        int cnt_pad = (cnt + 7) & ~7;
        if (cnt + lane < cnt_pad) lst[cnt + lane] = (unsigned short)ZROW;
        if (lane == 0) scnt[tt] = cnt_pad;
    }
    __syncthreads();
    for (int tt = wi; tt < 32; tt += 8) {
        int t = w * 32 + tt;
        if (t >= T_) continue;
        int row = b * T_ + t;
        int mine = scnt[tt];
        int pm = max(mine, scnt[tt ^ 1]);          // pair partner (t^1 stays in word)
        unsigned short* lst = &g_lists[(size_t)row * MAXL];
        for (int e = mine + lane; e < pm; e += 32) lst[e] = (unsigned short)ZROW;
        if (lane == 0) g_counts[row] = pm;
    }
}

// ---------------- K2b: sparse hidden GEMM (I = xs @ W_hid^T) -------------------
// Warp = row pair (b, t), (b, t+1); half-warp per row, float4 (2x f32x2) accum;
// one LDG.128 fetches both rows' index batches; LDS.128 W reads; f32x2 adds.
__global__ __launch_bounds__(1024, 1) void k_phaseA() {
    extern __shared__ float sW[];                // [(DIN+1)][HS]
    int hsIdx = blockIdx.x / NBG;
    int bg    = blockIdx.x % NBG;
    int h0    = hsIdx * HS;

    for (int e = threadIdx.x; e < (DIN + 1) * (HS / 4); e += blockDim.x) {
        int i = e >> 4, c = e & 15;
        ((float4*)sW)[e] = *(const float4*)&g_Wt[i * H_ + h0 + c * 4];
    }
    __syncthreads();

    int warpId = threadIdx.x >> 5, lane = threadIdx.x & 31;
    int half = lane >> 4, hl = lane & 15;
    const char* sWb = (const char*)sW + hl * 16;   // this thread's float4 column

    int bstart = bg * BPB;
    int nb = min(BPB, B_ - bstart);
    int npr = nb * (T_ / 2);

    for (int p = warpId; p < npr; p += 32) {
        int b  = bstart + p / (T_ / 2);
        int tp = (p % (T_ / 2)) * 2;
        int row = b * T_ + tp + half;              // my half's row
        int cnt = g_counts[row];                   // pair-max, multiple of 8
        const unsigned short* lst = &g_lists[(size_t)row * MAXL];
        unsigned long long a0 = 0ull, a1 = 0ull;   // packed {f32,f32} pairs
        for (int base = 0; base < cnt; base += 8) {
            uint4 pk = *(const uint4*)(lst + base);  // LDG.128, 2 sectors/warp
            unsigned j; ulonglong2 wv;
#define STEP(JE) \
            j = (JE); \
            wv = *(const ulonglong2*)(sWb + j * 256u); \
            asm("add.rn.f32x2 %0, %0, %1;" : "+l"(a0) : "l"(wv.x)); \
            asm("add.rn.f32x2 %0, %0, %1;" : "+l"(a1) : "l"(wv.y));
            STEP(pk.x & 0xFFFFu) STEP(pk.x >> 16)
            STEP(pk.y & 0xFFFFu) STEP(pk.y >> 16)
            STEP(pk.z & 0xFFFFu) STEP(pk.z >> 16)
            STEP(pk.w & 0xFFFFu) STEP(pk.w >> 16)
#undef STEP
        }
        ulonglong2 o; o.x = a0; o.y = a1;
        *(ulonglong2*)&g_I[(size_t)row * H_ + h0 + hl * 4] = o;
    }
}

// ---------------- K3: hidden LIF recurrence + spike-bit pack -------------------
__global__ void k_rec_hid(const float* __restrict__ hs0, const float* __restrict__ hv0) {
    int b  = blockIdx.x >> 2;
    int hq = blockIdx.x & 3;
    int h  = hq * 256 + threadIdx.x;
    int lane = threadIdx.x & 31;
    float hv = hv0[b * H_ + h];
    float hs = hs0[b * H_ + h];
    const float* Ip = &g_I[(size_t)(b * T_) * H_ + h];
    unsigned* hp = &g_hsb[(size_t)(b * T_) * (H_ / 32) + (h >> 5)];

    for (int t = 0; t < T_; t += 5) {            // 250 % 5 == 0
        float v[5];
#pragma unroll
        for (int k = 0; k < 5; k++) v[k] = Ip[(size_t)(t + k) * H_];
#pragma unroll
        for (int k = 0; k < 5; k++) {
            hv = hv * 0.5f * (1.0f - hs) + v[k];
            bool s = hv > 0.5f;
            hs = s ? 1.0f : 0.0f;
            unsigned m = __ballot_sync(0xffffffffu, s);
            if (lane == 0) hp[(size_t)(t + k) * (H_ / 32)] = m;
        }
    }
}

// ---------------- K4: out GEMM  O = hs @ W_out^T -------------------------------
__global__ void k_outgemm() {
    extern __shared__ float sWT[];               // [H_][DOUT] = 80 KB
    for (int e = threadIdx.x; e < H_ * DOUT / 4; e += blockDim.x)
        ((float4*)sWT)[e] = ((const float4*)g_WoT)[e];
    __syncthreads();

    int b = blockIdx.x;
    int wi = threadIdx.x >> 5, lane = threadIdx.x & 31;
    int t = wi * 32 + lane;
    bool valid = t < T_;
    int row = b * T_ + (valid ? t : 0);
    const unsigned* wp_ = &g_hsb[(size_t)row * (H_ / 32)];

    float acc[DOUT];
#pragma unroll
    for (int o = 0; o < DOUT; o++) acc[o] = 0.0f;

    for (int w = 0; w < H_ / 32; w++) {
        unsigned word = valid ? wp_[w] : 0u;
        if (word == 0u) continue;
#pragma unroll
        for (int bit = 0; bit < 32; bit++) {
            float m = (float)((word >> bit) & 1u);
            const float* base = &sWT[(w * 32 + bit) * DOUT];
#pragma unroll
            for (int o4 = 0; o4 < 5; o4++) {
                float4 wv = *(const float4*)(base + o4 * 4);
                acc[o4 * 4 + 0] = fmaf(m, wv.x, acc[o4 * 4 + 0]);
                acc[o4 * 4 + 1] = fmaf(m, wv.y, acc[o4 * 4 + 1]);
                acc[o4 * 4 + 2] = fmaf(m, wv.z, acc[o4 * 4 + 2]);
                acc[o4 * 4 + 3] = fmaf(m, wv.w, acc[o4 * 4 + 3]);
            }
        }
    }
    if (valid) {
        float4* op = (float4*)&g_O[(size_t)row * DOUT];
#pragma unroll
        for (int o4 = 0; o4 < 5; o4++)
            op[o4] = make_float4(acc[o4 * 4 + 0], acc[o4 * 4 + 1], acc[o4 * 4 + 2], acc[o4 * 4 + 3]);
    }
}

// ---------------- K5: out LIF recurrence + spike counts ------------------------
__global__ void k_rec_out(const float* __restrict__ os0, const float* __restrict__ ov0,
                          float* __restrict__ out) {
    int b = blockIdx.x * (blockDim.x / 32) + (threadIdx.x >> 5);
    int o = threadIdx.x & 31;
    if (b >= B_ || o >= DOUT) return;
    float ov = ov0[b * DOUT + o];
    float os = os0[b * DOUT + o];
    float cnt = 0.0f;
    const float* Op = &g_O[(size_t)(b * T_) * DOUT + o];
    for (int tb = 0; tb < T_; tb += 10) {        // 250 % 10 == 0
        float v[10];
#pragma unroll
        for (int k = 0; k < 10; k++) v[k] = Op[(size_t)(tb + k) * DOUT];
#pragma unroll
        for (int k = 0; k < 10; k++) {
            ov = ov * 0.5f * (1.0f - os) + v[k];
            os = (ov > 0.5f) ? 1.0f : 0.0f;
            cnt += os;
        }
    }
    out[b * DOUT + o] = cnt;
}

// ---------------- launch ------------------------------------------------------
extern "C" void kernel_launch(void* const* d_in, const int* in_sizes, int n_in,
                              void* d_out, int out_size) {
    const float* sd  = (const float*)d_in[0];   // spike_data [256,700,250]
    const float* Wh  = (const float*)d_in[1];   // W_hid [1024,700]
    const float* Wo  = (const float*)d_in[2];   // W_out [20,1024]
    const float* hs0 = (const float*)d_in[3];   // hid_spike0 [256,1024]
    const float* hv0 = (const float*)d_in[4];   // hid_volt0
    const float* os0 = (const float*)d_in[5];   // out_spike0 [256,20]
    const float* ov0 = (const float*)d_in[6];   // out_volt0
    float* out = (float*)d_out;                 // [256,20] fp32
    (void)in_sizes; (void)n_in; (void)out_size;

    cudaFuncSetAttribute(k_phaseA, cudaFuncAttributeMaxDynamicSharedMemorySize, (DIN + 1) * HS * 4);
    cudaFuncSetAttribute(k_outgemm, cudaFuncAttributeMaxDynamicSharedMemorySize, H_ * DOUT * 4);

    k_pack   <<<(B_ * DIN + 7) / 8, 256>>>(sd);
    k_tr     <<<256, 256>>>(Wh, Wo);
    k_lists  <<<B_ * NW, 256>>>();
    k_phaseA <<<16 * NBG, 1024, (DIN + 1) * HS * 4>>>();
    k_rec_hid<<<B_ * 4, 256>>>(hs0, hv0);
    k_outgemm<<<B_, 256, H_ * DOUT * 4>>>();
    k_rec_out<<<32, 256>>>(os0, ov0, out);
}

// round 7
// speedup vs baseline: 2.1430x; 1.0751x over previous
#include <cuda_runtime.h>
#include <cstdint>

#define B_    256
#define DIN   700
#define T_    250
#define H_    1024
#define DOUT  20
#define NW    8        // 32-bit words covering T_=250 bits
#define DINP  704      // padded DIN
#define MAXL  256      // max active inputs per (b,t) list (multiple of 8)
#define NROW  (B_*T_)  // 64000
#define HS    64       // h columns per phase-A block slice
#define NBG   9        // b-groups in phase A
#define BPB   29       // b per group (9*29=261 >= 256)
#define ZROW  DIN      // dummy zero W row index (row 700)

// ---------------- scratch (static device memory; no allocations) -------------
__device__ float          g_Wt[(DIN+1)*H_];                 // W_hid^T [i][h], row 700 = zeros
__device__ float          g_WoT[H_*DOUT];                   // W_out^T  [h][o]
__device__ unsigned       g_words[B_*NW*DINP];              // spike bits [(b*8+w)*704 + i], bit = t%32
__device__ unsigned short g_lists[(size_t)NROW*MAXL];       // active input indices per (b,t), pair-padded
__device__ int            g_counts[NROW];                   // pair-max counts (multiple of 8)
__device__ float          g_I[(size_t)NROW*H_];             // hidden input currents [b][t][h]
__device__ unsigned       g_hsb[(size_t)NROW*(H_/32)];      // hidden spike bits [b][t][h/32]

// ---------------- K0: pack spike_data -> bitmasks ----------------------------
__global__ void k_pack(const float* __restrict__ sd) {
    int gw   = blockIdx.x * 8 + (threadIdx.x >> 5);   // warp over B_*DIN rows
    int lane = threadIdx.x & 31;
    if (gw >= B_ * DIN) return;
    int b = gw / DIN, i = gw % DIN;
    const float* p = sd + ((size_t)b * DIN + i) * T_;
#pragma unroll
    for (int w = 0; w < NW; w++) {
        int t = w * 32 + lane;
        float v = (t < T_) ? p[t] : 0.0f;
        unsigned m = __ballot_sync(0xffffffffu, v > 0.5f);
        if (lane == 0) g_words[(b * NW + w) * DINP + i] = m;
    }
}

// ---------------- K1: transposes (W row 700 zeroed) ---------------------------
__global__ void k_tr(const float* __restrict__ Wh, const float* __restrict__ Wo) {
    int total = (DIN + 1) * H_ + H_ * DOUT;
    for (int e = blockIdx.x * blockDim.x + threadIdx.x; e < total; e += gridDim.x * blockDim.x) {
        if (e < (DIN + 1) * H_) {
            int i = e / H_, h = e % H_;
            g_Wt[e] = (i < DIN) ? Wh[h * DIN + i] : 0.0f;
        } else {
            int e2 = e - (DIN + 1) * H_;
            int h = e2 / DOUT, o = e2 % DOUT;
            g_WoT[e2] = Wo[o * H_ + h];
        }
    }
}

// ---------------- K2a: active-index lists, pair-padded -------------------------
__global__ void k_lists() {
    __shared__ unsigned sw[DINP];
    __shared__ int scnt[32];
    int b = blockIdx.x / NW, w = blockIdx.x % NW;
    for (int i = threadIdx.x; i < DIN; i += blockDim.x)
        sw[i] = g_words[(b * NW + w) * DINP + i];
    __syncthreads();
    int wi = threadIdx.x >> 5, lane = threadIdx.x & 31;
    for (int tt = wi; tt < 32; tt += 8) {
        int t = w * 32 + tt;
        if (t >= T_) { if (lane == 0) scnt[tt] = 0; continue; }
        int row = b * T_ + t;
        unsigned short* lst = &g_lists[(size_t)row * MAXL];
        int cnt = 0;
        for (int base = 0; base < DINP; base += 32) {
            int i = base + lane;
            unsigned hit = (i < DIN) ? ((sw[i] >> tt) & 1u) : 0u;
            unsigned m = __ballot_sync(0xffffffffu, hit != 0u);
            if (hit) {
                int pos = cnt + __popc(m & ((1u << lane) - 1u));
                if (pos < MAXL) lst[pos] = (unsigned short)i;
            }
            cnt += __popc(m);
        }
        cnt = min(cnt, MAXL);
        int cnt_pad = (cnt + 7) & ~7;
        if (cnt + lane < cnt_pad) lst[cnt + lane] = (unsigned short)ZROW;
        if (lane == 0) scnt[tt] = cnt_pad;
    }
    __syncthreads();
    for (int tt = wi; tt < 32; tt += 8) {
        int t = w * 32 + tt;
        if (t >= T_) continue;
        int row = b * T_ + t;
        int mine = scnt[tt];
        int pm = max(mine, scnt[tt ^ 1]);          // pair partner
        unsigned short* lst = &g_lists[(size_t)row * MAXL];
        for (int e = mine + lane; e < pm; e += 32) lst[e] = (unsigned short)ZROW;
        if (lane == 0) g_counts[row] = pm;
    }
}

// ---------------- K2b: sparse hidden GEMM (I = xs @ W_hid^T) -------------------
// Warp = row pair; half-warp per row; f32x2 adds; prefetched index LDG.128.
__global__ __launch_bounds__(1024, 1) void k_phaseA() {
    extern __shared__ float sW[];                // [(DIN+1)][HS]
    int hsIdx = blockIdx.x / NBG;
    int bg    = blockIdx.x % NBG;
    int h0    = hsIdx * HS;

    for (int e = threadIdx.x; e < (DIN + 1) * (HS / 4); e += blockDim.x) {
        int i = e >> 4, c = e & 15;
        ((float4*)sW)[e] = *(const float4*)&g_Wt[i * H_ + h0 + c * 4];
    }
    __syncthreads();

    int warpId = threadIdx.x >> 5, lane = threadIdx.x & 31;
    int half = lane >> 4, hl = lane & 15;
    const char* sWb = (const char*)sW + hl * 16;   // this thread's float4 column

    int bstart = bg * BPB;
    int nb = min(BPB, B_ - bstart);
    int npr = nb * (T_ / 2);

    for (int p = warpId; p < npr; p += 32) {
        int b  = bstart + p / (T_ / 2);
        int tp = (p % (T_ / 2)) * 2;
        int row = b * T_ + tp + half;              // my half's row
        int cnt = g_counts[row];                   // pair-max, multiple of 8
        const unsigned short* lst = &g_lists[(size_t)row * MAXL];
        unsigned long long a0 = 0ull, a1 = 0ull;   // packed {f32,f32} pairs
        uint4 pk = *(const uint4*)lst;             // prefetch first batch
        for (int base = 0; base < cnt; base += 8) {
            uint4 cur = pk;
            if (base + 8 < cnt) pk = *(const uint4*)(lst + base + 8);
            unsigned j; ulonglong2 wv;
#define STEP(JE) \
            j = (JE); \
            wv = *(const ulonglong2*)(sWb + j * 256u); \
            asm("add.rn.f32x2 %0, %0, %1;" : "+l"(a0) : "l"(wv.x)); \
            asm("add.rn.f32x2 %0, %0, %1;" : "+l"(a1) : "l"(wv.y));
            STEP(cur.x & 0xFFFFu) STEP(cur.x >> 16)
            STEP(cur.y & 0xFFFFu) STEP(cur.y >> 16)
            STEP(cur.z & 0xFFFFu) STEP(cur.z >> 16)
            STEP(cur.w & 0xFFFFu) STEP(cur.w >> 16)
#undef STEP
        }
        ulonglong2 o; o.x = a0; o.y = a1;
        *(ulonglong2*)&g_I[(size_t)row * H_ + h0 + hl * 4] = o;
    }
}

// ---------------- K3: hidden LIF recurrence + spike-bit pack -------------------
__global__ void k_rec_hid(const float* __restrict__ hs0, const float* __restrict__ hv0) {
    int b  = blockIdx.x >> 2;
    int hq = blockIdx.x & 3;
    int h  = hq * 256 + threadIdx.x;
    int lane = threadIdx.x & 31;
    float hv = hv0[b * H_ + h];
    float hs = hs0[b * H_ + h];
    const float* Ip = &g_I[(size_t)(b * T_) * H_ + h];
    unsigned* hp = &g_hsb[(size_t)(b * T_) * (H_ / 32) + (h >> 5)];

    for (int t = 0; t < T_; t += 5) {            // 250 % 5 == 0
        float v[5];
#pragma unroll
        for (int k = 0; k < 5; k++) v[k] = Ip[(size_t)(t + k) * H_];
#pragma unroll
        for (int k = 0; k < 5; k++) {
            hv = hv * 0.5f * (1.0f - hs) + v[k];
            bool s = hv > 0.5f;
            hs = s ? 1.0f : 0.0f;
            unsigned m = __ballot_sync(0xffffffffu, s);
            if (lane == 0) hp[(size_t)(t + k) * (H_ / 32)] = m;
        }
    }
}

// ---------------- K4: out GEMM (sparse ffs walk) + fused out recurrence --------
// Block = one batch b. Thread t computes O[t][0:20] by walking set spike bits,
// stages to smem, then 20 threads run the output LIF recurrence over t.
__global__ __launch_bounds__(256) void k_outgemm(const float* __restrict__ os0,
                                                 const float* __restrict__ ov0,
                                                 float* __restrict__ out) {
    extern __shared__ float smem_[];             // sWT [H_*20] + sO [256*20]
    float* sWT = smem_;
    float* sO  = smem_ + H_ * DOUT;
    for (int e = threadIdx.x; e < H_ * DOUT / 4; e += blockDim.x)
        ((float4*)sWT)[e] = ((const float4*)g_WoT)[e];
    __syncthreads();

    int b = blockIdx.x, t = threadIdx.x;
    if (t < T_) {
        const unsigned* wp_ = &g_hsb[(size_t)(b * T_ + t) * (H_ / 32)];
        float2 acc[10];
#pragma unroll
        for (int o = 0; o < 10; o++) acc[o] = make_float2(0.0f, 0.0f);
#pragma unroll 4
        for (int w = 0; w < H_ / 32; w++) {
            unsigned word = wp_[w];
            while (word) {
                int bit = __ffs(word) - 1;
                word &= word - 1;
                const float2* base = (const float2*)&sWT[(w * 32 + bit) * DOUT];
#pragma unroll
                for (int o = 0; o < 10; o++) {
                    float2 v = base[o];
                    acc[o].x += v.x; acc[o].y += v.y;
                }
            }
        }
        float2* od = (float2*)&sO[t * DOUT];
#pragma unroll
        for (int o = 0; o < 10; o++) od[o] = acc[o];
    }
    __syncthreads();

    if (t < DOUT) {
        float ov = ov0[b * DOUT + t];
        float os = os0[b * DOUT + t];
        float cnt = 0.0f;
        for (int tt = 0; tt < T_; tt++) {
            float v = sO[tt * DOUT + t];
            ov = ov * 0.5f * (1.0f - os) + v;
            os = (ov > 0.5f) ? 1.0f : 0.0f;
            cnt += os;
        }
        out[b * DOUT + t] = cnt;
    }
}

// ---------------- launch ------------------------------------------------------
extern "C" void kernel_launch(void* const* d_in, const int* in_sizes, int n_in,
                              void* d_out, int out_size) {
    const float* sd  = (const float*)d_in[0];   // spike_data [256,700,250]
    const float* Wh  = (const float*)d_in[1];   // W_hid [1024,700]
    const float* Wo  = (const float*)d_in[2];   // W_out [20,1024]
    const float* hs0 = (const float*)d_in[3];   // hid_spike0 [256,1024]
    const float* hv0 = (const float*)d_in[4];   // hid_volt0
    const float* os0 = (const float*)d_in[5];   // out_spike0 [256,20]
    const float* ov0 = (const float*)d_in[6];   // out_volt0
    float* out = (float*)d_out;                 // [256,20] fp32
    (void)in_sizes; (void)n_in; (void)out_size;

    int outg_smem = (H_ * DOUT + 256 * DOUT) * 4;   // 80 KB + 20 KB
    cudaFuncSetAttribute(k_phaseA, cudaFuncAttributeMaxDynamicSharedMemorySize, (DIN + 1) * HS * 4);
    cudaFuncSetAttribute(k_outgemm, cudaFuncAttributeMaxDynamicSharedMemorySize, outg_smem);

    k_pack   <<<(B_ * DIN + 7) / 8, 256>>>(sd);
    k_tr     <<<256, 256>>>(Wh, Wo);
    k_lists  <<<B_ * NW, 256>>>();
    k_phaseA <<<16 * NBG, 1024, (DIN + 1) * HS * 4>>>();
    k_rec_hid<<<B_ * 4, 256>>>(hs0, hv0);
    k_outgemm<<<B_, 256, outg_smem>>>(os0, ov0, out);
}